// round 13
// baseline (speedup 1.0000x reference)
#include <cuda_runtime.h>
#include <cuda_fp16.h>
#include <cstdint>

// Problem constants: B_=2048, N=49, C=384, H=12, d=32, nW=64
#define BWIN   2048
#define NTOK   49
#define CDIM   384
#define HNUM   12
#define DHEAD  32
#define NWIN   64
#define MROWS  (BWIN * NTOK)     // 100352
#define QKVC   (3 * CDIM)        // 1152
#define KDIM   384

// GEMM tiling: 128x128 CTA tile, B strip resident, persistent over M-tiles
#define GBM   128
#define GBN   128
#define GKC   64
#define NCH   6                  // 384 / 64
#define ROWB  144
#define A_ST  (GBM * ROWB)       // 18432
#define B_ST  (GBN * ROWB)       // 18432
#define SMEM_GEMM (NCH * B_ST + 3 * A_ST)   // 165888
#define MTILES (MROWS / GBM)     // 784
#define MTQ   7                  // m-tiles per CTA (qkv): 784 = 112*7
#define MTP   4                  // m-tiles per CTA (proj): 784 = 196*4

#define PX_BLKS  37632
#define WQ_BLKS  1728
#define WP_BLKS  576
#define PAD_BLKS 6144

#define BSTR 50

// -------------------- device scratch --------------------------------------
__device__ __align__(16) __half g_xh  [(size_t)MROWS * KDIM];
__device__ __align__(16) __half g_attf[(size_t)MROWS * CDIM];
__device__ __align__(16) __half g_qkh [(size_t)MROWS * 768];
__device__ __align__(16) __half g_vt  [(size_t)BWIN * CDIM * 64];
__device__ __align__(16) __half g_wq  [(size_t)QKVC * KDIM];
__device__ __align__(16) __half g_wp  [(size_t)CDIM * KDIM];

// -------------------- PTX helpers -----------------------------------------
__device__ __forceinline__ uint32_t smem_u32(const void* p) {
    uint32_t a;
    asm("{ .reg .u64 t; cvta.to.shared.u64 t, %1; cvt.u32.u64 %0, t; }"
        : "=r"(a) : "l"(p));
    return a;
}
__device__ __forceinline__ void cp16(uint32_t s, const void* g) {
    asm volatile("cp.async.cg.shared.global [%0], [%1], 16;" :: "r"(s), "l"(g));
}
__device__ __forceinline__ void cp_commit() {
    asm volatile("cp.async.commit_group;" ::: "memory");
}
__device__ __forceinline__ void ldsm4(uint32_t* r, uint32_t addr) {
    asm volatile("ldmatrix.sync.aligned.m8n8.x4.shared.b16 {%0,%1,%2,%3}, [%4];"
        : "=r"(r[0]), "=r"(r[1]), "=r"(r[2]), "=r"(r[3]) : "r"(addr));
}
__device__ __forceinline__ void mma16816(float* d, const uint32_t* a, const uint32_t* b) {
    asm volatile(
        "mma.sync.aligned.m16n8k16.row.col.f32.f16.f16.f32 "
        "{%0,%1,%2,%3}, {%4,%5,%6,%7}, {%8,%9}, {%0,%1,%2,%3};"
        : "+f"(d[0]), "+f"(d[1]), "+f"(d[2]), "+f"(d[3])
        : "r"(a[0]), "r"(a[1]), "r"(a[2]), "r"(a[3]), "r"(b[0]), "r"(b[1]));
}
__device__ __forceinline__ uint32_t pack2(__half lo, __half hi) {
    return (uint32_t)__half_as_ushort(lo) | ((uint32_t)__half_as_ushort(hi) << 16);
}

// -------------------- fused prep -------------------------------------------
__global__ __launch_bounds__(256)
void prep_all_kernel(const float* __restrict__ x,
                     const float* __restrict__ qkv_w,
                     const float* __restrict__ proj_w)
{
    const int bid = blockIdx.x;
    const int tid = threadIdx.x;

    if (bid < PX_BLKS) {
        size_t id = (size_t)bid * 256 + tid;
        size_t row = id / 96;
        int c4 = (int)(id % 96) * 4;
        float4 v = *reinterpret_cast<const float4*>(&x[row * KDIM + c4]);
        __half h[4];
        h[0] = __float2half_rn(v.x); h[1] = __float2half_rn(v.y);
        h[2] = __float2half_rn(v.z); h[3] = __float2half_rn(v.w);
        *reinterpret_cast<uint2*>(&g_xh[row * KDIM + c4]) = *reinterpret_cast<uint2*>(h);
    } else if (bid < PX_BLKS + WQ_BLKS) {
        int id = (bid - PX_BLKS) * 256 + tid;
        if (id < KDIM * QKVC) {
            int k = id / QKVC, n = id % QKVC;
            g_wq[(size_t)n * KDIM + k] = __float2half_rn(qkv_w[(size_t)k * QKVC + n]);
        }
    } else if (bid < PX_BLKS + WQ_BLKS + WP_BLKS) {
        int id = (bid - PX_BLKS - WQ_BLKS) * 256 + tid;
        if (id < KDIM * CDIM) {
            int k = id / CDIM, n = id % CDIM;
            g_wp[(size_t)n * KDIM + k] = __float2half_rn(proj_w[(size_t)k * CDIM + n]);
        }
    } else {
        size_t s = (size_t)(bid - PX_BLKS - WQ_BLKS - WP_BLKS) * 256 + tid;
        size_t row = s >> 1;
        if (row < (size_t)BWIN * CDIM) {
            uint4* p = reinterpret_cast<uint4*>(
                reinterpret_cast<char*>(g_vt) + row * 128 + 96 + (s & 1) * 16);
            *p = make_uint4(0, 0, 0, 0);
        }
    }
}

// -------------------- persistent GEMM (B-resident) --------------------------
// mode 0: fp32 out to Cv (ldc stride)                        (proj)
// mode 3: qkv fused — col<768: fp16 -> g_qkh; col>=768: scatter -> g_vt
// Each CTA: loads its 128-col B strip (all 6 K-chunks) into smem once, then
// streams `mtiles` consecutive M-tiles of A through a 3-stage cp.async ring.
__global__ __launch_bounds__(256, 1)
void gemm_fp16_kernel(const __half* __restrict__ Ab, int lda,
                      const __half* __restrict__ Bt,
                      const float* __restrict__ bias,
                      void* __restrict__ Cv, int ldc, int mode, int mtiles)
{
    extern __shared__ char smem[];
    const uint32_t s0 = smem_u32(smem);
    const uint32_t sB = s0;                    // 6 resident B chunks
    const uint32_t sA = s0 + NCH * B_ST;       // 3-stage A ring

    const int tid  = threadIdx.x;
    const int wid  = tid >> 5;
    const int lane = tid & 31;
    const int wm   = wid >> 1;
    const int wn   = wid & 1;
    const int bn   = blockIdx.x * GBN;
    const int bm0  = blockIdx.y * mtiles * GBM;

    const int lrow = tid >> 3;
    const int seg  = tid & 7;

    const int a_r  = (lane & 7) + ((lane >> 3) & 1) * 8;
    const int a_cb = (lane >> 4) * 16;
    const int b_r  = (lane & 7) + ((lane >> 4) & 1) * 8;
    const int b_cb = ((lane >> 3) & 1) * 16;

    auto issueA = [&](int t) {
        const int mt = t / NCH, kc = t - mt * NCH;
        const size_t base = (size_t)(bm0 + mt * GBM);
        const uint32_t sa = sA + (t % 3) * A_ST;
#pragma unroll
        for (int i = 0; i < 4; ++i) {
            int r = lrow + i * 32;
            cp16(sa + r * ROWB + seg * 16,
                 Ab + (base + r) * lda + kc * GKC + seg * 8);
        }
    };

    // B strip: all 6 chunks, committed together with A(t=0) as group 0
#pragma unroll
    for (int kc = 0; kc < NCH; ++kc) {
#pragma unroll
        for (int i = 0; i < 4; ++i) {
            int r = lrow + i * 32;
            cp16(sB + kc * B_ST + r * ROWB + seg * 16,
                 Bt + (size_t)(bn + r) * KDIM + kc * GKC + seg * 8);
        }
    }
    issueA(0); cp_commit();      // group 0 = B strip + A0
    issueA(1); cp_commit();      // group 1 = A1

    const int total = mtiles * NCH;

    for (int mt = 0; mt < mtiles; ++mt) {
        float acc[2][8][4];
#pragma unroll
        for (int i = 0; i < 2; ++i)
#pragma unroll
            for (int j = 0; j < 8; ++j)
#pragma unroll
                for (int q = 0; q < 4; ++q) acc[i][j][q] = 0.f;

        for (int kc = 0; kc < NCH; ++kc) {
            const int t = mt * NCH + kc;
            if (t < total - 1)
                asm volatile("cp.async.wait_group 1;" ::: "memory");
            else
                asm volatile("cp.async.wait_group 0;" ::: "memory");
            __syncthreads();

            if (t + 2 < total) { issueA(t + 2); cp_commit(); }

            const uint32_t abase = sA + (t % 3) * A_ST + (wm * 32 + a_r) * ROWB + a_cb;
            const uint32_t bbase = sB + kc * B_ST + (wn * 64 + b_r) * ROWB + b_cb;

#pragma unroll
            for (int ks = 0; ks < 4; ++ks) {
                const int kb = ks * 32;
                uint32_t af[2][4];
#pragma unroll
                for (int fm = 0; fm < 2; ++fm)
                    ldsm4(af[fm], abase + fm * 16 * ROWB + kb);
                uint32_t bfr[8][2];
#pragma unroll
                for (int j = 0; j < 4; ++j) {
                    uint32_t r[4];
                    ldsm4(r, bbase + j * 16 * ROWB + kb);
                    bfr[2 * j][0] = r[0]; bfr[2 * j][1] = r[1];
                    bfr[2 * j + 1][0] = r[2]; bfr[2 * j + 1][1] = r[3];
                }
#pragma unroll
                for (int fm = 0; fm < 2; ++fm)
#pragma unroll
                    for (int fn = 0; fn < 8; ++fn)
                        mma16816(acc[fm][fn], af[fm], bfr[fn]);
            }
        }

        // epilogue for this M-tile (register->gmem; A pipeline keeps flowing)
        const int bm = bm0 + mt * GBM;
#pragma unroll
        for (int fm = 0; fm < 2; ++fm) {
            const int row0 = bm + wm * 32 + fm * 16 + (lane >> 2);
            const int b0 = row0 / NTOK,        n0 = row0 - b0 * NTOK;
            const int b1 = (row0 + 8) / NTOK,  n1 = (row0 + 8) - b1 * NTOK;
#pragma unroll
            for (int fn = 0; fn < 8; ++fn) {
                const int col = bn + wn * 64 + fn * 8 + (lane & 3) * 2;
                const float b0f = __ldg(&bias[col]);
                const float b1f = __ldg(&bias[col + 1]);
                const float o0 = acc[fm][fn][0] + b0f, o1 = acc[fm][fn][1] + b1f;
                const float o2 = acc[fm][fn][2] + b0f, o3 = acc[fm][fn][3] + b1f;
                if (mode == 0) {
                    float* C = (float*)Cv;
                    *reinterpret_cast<float2*>(&C[(size_t)row0 * ldc + col]) =
                        make_float2(o0, o1);
                    *reinterpret_cast<float2*>(&C[(size_t)(row0 + 8) * ldc + col]) =
                        make_float2(o2, o3);
                } else if (col < 768) {
                    *reinterpret_cast<uint32_t*>(&g_qkh[(size_t)row0 * 768 + col]) =
                        pack2(__float2half_rn(o0), __float2half_rn(o1));
                    *reinterpret_cast<uint32_t*>(&g_qkh[(size_t)(row0 + 8) * 768 + col]) =
                        pack2(__float2half_rn(o2), __float2half_rn(o3));
                } else {
                    const int cv = col - 768;
                    const size_t i0 = ((size_t)b0 * CDIM + cv) * 64 + n0;
                    const size_t i1 = ((size_t)b1 * CDIM + cv) * 64 + n1;
                    g_vt[i0]      = __float2half_rn(o0);
                    g_vt[i0 + 64] = __float2half_rn(o1);
                    g_vt[i1]      = __float2half_rn(o2);
                    g_vt[i1 + 64] = __float2half_rn(o3);
                }
            }
        }
    }
}

// -------------------- MMA attention (unchanged from R12) --------------------
__global__ __launch_bounds__(128)
void attn_mma_kernel(const float* __restrict__ relb,
                     const float* __restrict__ mask)
{
    __shared__ float bias_s[NTOK * BSTR];

    const int w = blockIdx.x, h = blockIdx.y, zh = blockIdx.z;
    const int tid = threadIdx.x, warp = tid >> 5, lane = tid & 31;
    const int kq = lane >> 2;
    const int kc = (lane & 3) * 2;

    {
        const float* rb = relb + (size_t)h * NTOK * NTOK;
        const float* mk = mask + (size_t)w * NTOK * NTOK;
        for (int i = tid; i < NTOK * NTOK; i += 128)
            bias_s[(i / NTOK) * BSTR + (i % NTOK)] = rb[i] + mk[i];
    }
    __syncthreads();

    const float scale = 0.17677669529663687f;

    for (int win = 0; win < 4; ++win) {
        const int j = zh * 16 + warp * 4 + win;
        const int b = j * 64 + w;
        const __half* qk  = g_qkh + (size_t)b * NTOK * 768 + h * DHEAD;
        const __half* vth = g_vt + ((size_t)b * CDIM + h * DHEAD) * 64;

        uint32_t kf[7][2][2];
#pragma unroll
        for (int nt = 0; nt < 7; ++nt) {
            const int key = nt * 8 + kq;
            const bool ok = (key < NTOK);
            const __half* p = qk + (size_t)(ok ? key : 0) * 768 + 384;
#pragma unroll
            for (int ks = 0; ks < 2; ++ks) {
                const int d = ks * 16 + kc;
                kf[nt][ks][0] = ok ? *reinterpret_cast<const uint32_t*>(p + d)     : 0u;
                kf[nt][ks][1] = ok ? *reinterpret_cast<const uint32_t*>(p + d + 8) : 0u;
            }
        }
        uint32_t vhf[4][4][2];
#pragma unroll
        for (int nt = 0; nt < 4; ++nt) {
            const size_t drow = (size_t)(nt * 8 + kq) * 64;
#pragma unroll
            for (int kt = 0; kt < 4; ++kt) {
#pragma unroll
                for (int r2 = 0; r2 < 2; ++r2) {
                    const int k0 = kt * 16 + kc + r2 * 8;
                    vhf[nt][kt][r2] = *reinterpret_cast<const uint32_t*>(vth + drow + k0);
                }
            }
        }

        for (int mt = 0; mt < 4; ++mt) {
            const int row = mt * 16 + kq;
            const bool r0ok = (row < NTOK), r1ok = (row + 8 < NTOK);
            const __half* q0 = qk + (size_t)(r0ok ? row : 0) * 768;
            const __half* q1 = qk + (size_t)(r1ok ? row + 8 : 0) * 768;

            uint32_t qf[2][4];
#pragma unroll
            for (int ks = 0; ks < 2; ++ks) {
                const int d = ks * 16 + kc;
                qf[ks][0] = r0ok ? *reinterpret_cast<const uint32_t*>(q0 + d)     : 0u;
                qf[ks][1] = r1ok ? *reinterpret_cast<const uint32_t*>(q1 + d)     : 0u;
                qf[ks][2] = r0ok ? *reinterpret_cast<const uint32_t*>(q0 + d + 8) : 0u;
                qf[ks][3] = r1ok ? *reinterpret_cast<const uint32_t*>(q1 + d + 8) : 0u;
            }

            float sf[7][4];
#pragma unroll
            for (int nt = 0; nt < 7; ++nt) {
                sf[nt][0] = sf[nt][1] = sf[nt][2] = sf[nt][3] = 0.f;
                mma16816(sf[nt], qf[0], kf[nt][0]);
                mma16816(sf[nt], qf[1], kf[nt][1]);
            }

            const int n0 = (row < 48) ? row : 48;
            const int n1 = (row + 8 < 48) ? (row + 8) : 48;
            float sum0 = 0.f, sum1 = 0.f;
#pragma unroll
            for (int nt = 0; nt < 7; ++nt) {
                const int key = nt * 8 + kc;
                const float2 bq0 = *reinterpret_cast<const float2*>(&bias_s[n0 * BSTR + key]);
                const float2 bq1 = *reinterpret_cast<const float2*>(&bias_s[n1 * BSTR + key]);
                float e0 = __expf(sf[nt][0] * scale + bq0.x);
                float e1 = __expf(sf[nt][1] * scale + bq0.y);
                float e2 = __expf(sf[nt][2] * scale + bq1.x);
                float e3 = __expf(sf[nt][3] * scale + bq1.y);
                if (nt == 6) {
                    if (kc != 0) { e0 = 0.f; e2 = 0.f; }
                    e1 = 0.f; e3 = 0.f;
                }
                sf[nt][0] = e0; sf[nt][1] = e1; sf[nt][2] = e2; sf[nt][3] = e3;
                sum0 += e0 + e1; sum1 += e2 + e3;
            }
            sum0 += __shfl_xor_sync(0xffffffffu, sum0, 1);
            sum0 += __shfl_xor_sync(0xffffffffu, sum0, 2);
            sum1 += __shfl_xor_sync(0xffffffffu, sum1, 1);
            sum1 += __shfl_xor_sync(0xffffffffu, sum1, 2);
            const float inv0 = 1.f / sum0, inv1 = 1.f / sum1;

            float of[4][4];
#pragma unroll
            for (int nt = 0; nt < 4; ++nt)
                of[nt][0] = of[nt][1] = of[nt][2] = of[nt][3] = 0.f;

#pragma unroll
            for (int kt = 0; kt < 4; ++kt) {
                float e[8];
                e[0] = sf[2 * kt][0]; e[1] = sf[2 * kt][1];
                e[2] = sf[2 * kt][2]; e[3] = sf[2 * kt][3];
                if (2 * kt + 1 < 7) {
                    e[4] = sf[2 * kt + 1][0]; e[5] = sf[2 * kt + 1][1];
                    e[6] = sf[2 * kt + 1][2]; e[7] = sf[2 * kt + 1][3];
                } else {
                    e[4] = e[5] = e[6] = e[7] = 0.f;
                }
                __half hb[8], lb[8];
#pragma unroll
                for (int i = 0; i < 8; ++i) {
                    hb[i] = __float2half_rn(e[i]);
                    lb[i] = __float2half_rn(e[i] - __half2float(hb[i]));
                }
                uint32_t ph[4], pl[4];
                ph[0] = pack2(hb[0], hb[1]); ph[1] = pack2(hb[2], hb[3]);
                ph[2] = pack2(hb[4], hb[5]); ph[3] = pack2(hb[6], hb[7]);
                pl[0] = pack2(lb[0], lb[1]); pl[1] = pack2(lb[2], lb[3]);
                pl[2] = pack2(lb[4], lb[5]); pl[3] = pack2(lb[6], lb[7]);
#pragma unroll
                for (int nt = 0; nt < 4; ++nt) {
                    mma16816(of[nt], ph, vhf[nt][kt]);
                    mma16816(of[nt], pl, vhf[nt][kt]);
                }
            }

            const size_t r0 = ((size_t)b * NTOK + row) * CDIM + h * DHEAD;
            const size_t r1 = ((size_t)b * NTOK + row + 8) * CDIM + h * DHEAD;
#pragma unroll
            for (int nt = 0; nt < 4; ++nt) {
                const int d = nt * 8 + kc;
                if (r0ok) {
                    *reinterpret_cast<uint32_t*>(&g_attf[r0 + d]) =
                        pack2(__float2half_rn(of[nt][0] * inv0),
                              __float2half_rn(of[nt][1] * inv0));
                }
                if (r1ok) {
                    *reinterpret_cast<uint32_t*>(&g_attf[r1 + d]) =
                        pack2(__float2half_rn(of[nt][2] * inv1),
                              __float2half_rn(of[nt][3] * inv1));
                }
            }
        }
    }
}

// ---------------------------------------------------------------------------
extern "C" void kernel_launch(void* const* d_in, const int* in_sizes, int n_in,
                              void* d_out, int out_size)
{
    const float* x      = (const float*)d_in[0];
    const float* mask   = (const float*)d_in[1];
    const float* qkv_w  = (const float*)d_in[2];
    const float* qkv_b  = (const float*)d_in[3];
    const float* proj_w = (const float*)d_in[4];
    const float* proj_b = (const float*)d_in[5];
    const float* relb   = (const float*)d_in[6];
    float* out = (float*)d_out;

    void *p_xh, *p_attf, *p_wq, *p_wp;
    cudaGetSymbolAddress(&p_xh,   g_xh);
    cudaGetSymbolAddress(&p_attf, g_attf);
    cudaGetSymbolAddress(&p_wq,   g_wq);
    cudaGetSymbolAddress(&p_wp,   g_wp);

    cudaFuncSetAttribute(gemm_fp16_kernel,
                         cudaFuncAttributeMaxDynamicSharedMemorySize, SMEM_GEMM);

    // 0) fused preps
    prep_all_kernel<<<PX_BLKS + WQ_BLKS + WP_BLKS + PAD_BLKS, 256>>>(x, qkv_w, proj_w);

    // 1) fused QKV GEMM: persistent, 7 M-tiles per CTA
    {
        dim3 grid(QKVC / GBN, MTILES / MTQ);   // 9 x 112
        gemm_fp16_kernel<<<grid, 256, SMEM_GEMM>>>(
            (const __half*)p_xh, KDIM, (const __half*)p_wq,
            qkv_b, nullptr, 0, 3, MTQ);
    }
    // 2) MMA attention
    {
        dim3 grid(NWIN, HNUM, 2);
        attn_mma_kernel<<<grid, 128>>>(relb, mask);
    }
    // 3) projection GEMM: persistent, 4 M-tiles per CTA
    {
        dim3 grid(CDIM / GBN, MTILES / MTP);   // 3 x 196
        gemm_fp16_kernel<<<grid, 256, SMEM_GEMM>>>(
            (const __half*)p_attf, CDIM, (const __half*)p_wp,
            proj_b, out, CDIM, 0, MTP);
    }
}

// round 14
// speedup vs baseline: 1.0982x; 1.0982x over previous
#include <cuda_runtime.h>
#include <cuda_fp16.h>
#include <cstdint>

// Problem constants: B_=2048, N=49, C=384, H=12, d=32, nW=64
#define BWIN   2048
#define NTOK   49
#define CDIM   384
#define HNUM   12
#define DHEAD  32
#define NWIN   64
#define MROWS  (BWIN * NTOK)     // 100352
#define QKVC   (3 * CDIM)        // 1152
#define KDIM   384

// GEMM tiling (R12 shape: 2 CTAs/SM), pipelined across MT_PER M-tiles
#define GBM   128
#define GBN   128
#define GKC   64
#define NCH   6                  // 384 / 64
#define NSTG  3
#define ROWB  144
#define A_ST  (GBM * ROWB)
#define B_ST  (GBN * ROWB)
#define STG_B (A_ST + B_ST)
#define SMEM_GEMM (NSTG * STG_B) // 110592 -> 2 CTAs/SM
#define MTILES (MROWS / GBM)     // 784
#define MT_PER 2                 // M-tiles chained per CTA (784 = 392*2)

#define PX_BLKS  37632
#define WQ_BLKS  1728
#define WP_BLKS  576
#define PAD_BLKS 6144

#define BSTR 50
#define SCALE 0.17677669529663687f

// -------------------- device scratch --------------------------------------
__device__ __align__(16) __half g_xh  [(size_t)MROWS * KDIM];
__device__ __align__(16) __half g_attf[(size_t)MROWS * CDIM];
__device__ __align__(16) __half g_qkh [(size_t)MROWS * 768];
__device__ __align__(16) __half g_vt  [(size_t)BWIN * CDIM * 64];
__device__ __align__(16) __half g_wq  [(size_t)QKVC * KDIM];
__device__ __align__(16) __half g_wp  [(size_t)CDIM * KDIM];

// -------------------- PTX helpers -----------------------------------------
__device__ __forceinline__ uint32_t smem_u32(const void* p) {
    uint32_t a;
    asm("{ .reg .u64 t; cvta.to.shared.u64 t, %1; cvt.u32.u64 %0, t; }"
        : "=r"(a) : "l"(p));
    return a;
}
__device__ __forceinline__ void cp16(uint32_t s, const void* g) {
    asm volatile("cp.async.cg.shared.global [%0], [%1], 16;" :: "r"(s), "l"(g));
}
__device__ __forceinline__ void cp_commit() {
    asm volatile("cp.async.commit_group;" ::: "memory");
}
__device__ __forceinline__ void ldsm4(uint32_t* r, uint32_t addr) {
    asm volatile("ldmatrix.sync.aligned.m8n8.x4.shared.b16 {%0,%1,%2,%3}, [%4];"
        : "=r"(r[0]), "=r"(r[1]), "=r"(r[2]), "=r"(r[3]) : "r"(addr));
}
__device__ __forceinline__ void mma16816(float* d, const uint32_t* a, const uint32_t* b) {
    asm volatile(
        "mma.sync.aligned.m16n8k16.row.col.f32.f16.f16.f32 "
        "{%0,%1,%2,%3}, {%4,%5,%6,%7}, {%8,%9}, {%0,%1,%2,%3};"
        : "+f"(d[0]), "+f"(d[1]), "+f"(d[2]), "+f"(d[3])
        : "r"(a[0]), "r"(a[1]), "r"(a[2]), "r"(a[3]), "r"(b[0]), "r"(b[1]));
}
__device__ __forceinline__ uint32_t pack2(__half lo, __half hi) {
    return (uint32_t)__half_as_ushort(lo) | ((uint32_t)__half_as_ushort(hi) << 16);
}

// -------------------- fused prep -------------------------------------------
__global__ __launch_bounds__(256)
void prep_all_kernel(const float* __restrict__ x,
                     const float* __restrict__ qkv_w,
                     const float* __restrict__ proj_w)
{
    const int bid = blockIdx.x;
    const int tid = threadIdx.x;

    if (bid < PX_BLKS) {
        size_t id = (size_t)bid * 256 + tid;
        size_t row = id / 96;
        int c4 = (int)(id % 96) * 4;
        float4 v = *reinterpret_cast<const float4*>(&x[row * KDIM + c4]);
        __half h[4];
        h[0] = __float2half_rn(v.x); h[1] = __float2half_rn(v.y);
        h[2] = __float2half_rn(v.z); h[3] = __float2half_rn(v.w);
        *reinterpret_cast<uint2*>(&g_xh[row * KDIM + c4]) = *reinterpret_cast<uint2*>(h);
    } else if (bid < PX_BLKS + WQ_BLKS) {
        int id = (bid - PX_BLKS) * 256 + tid;
        if (id < KDIM * QKVC) {
            int k = id / QKVC, n = id % QKVC;
            g_wq[(size_t)n * KDIM + k] = __float2half_rn(qkv_w[(size_t)k * QKVC + n]);
        }
    } else if (bid < PX_BLKS + WQ_BLKS + WP_BLKS) {
        int id = (bid - PX_BLKS - WQ_BLKS) * 256 + tid;
        if (id < KDIM * CDIM) {
            int k = id / CDIM, n = id % CDIM;
            g_wp[(size_t)n * KDIM + k] = __float2half_rn(proj_w[(size_t)k * CDIM + n]);
        }
    } else {
        size_t s = (size_t)(bid - PX_BLKS - WQ_BLKS - WP_BLKS) * 256 + tid;
        size_t row = s >> 1;
        if (row < (size_t)BWIN * CDIM) {
            uint4* p = reinterpret_cast<uint4*>(
                reinterpret_cast<char*>(g_vt) + row * 128 + 96 + (s & 1) * 16);
            *p = make_uint4(0, 0, 0, 0);
        }
    }
}

// -------------------- GEMM (R12 shape, 2 chained M-tiles) --------------------
// mode 0: fp32 out to Cv (ldc stride)                         (proj)
// mode 3: qkv fused — col<384: q*SCALE fp16 -> g_qkh;
//                     384<=col<768: k fp16 -> g_qkh;
//                     col>=768: v fp16 scatter -> g_vt
__global__ __launch_bounds__(256, 2)
void gemm_fp16_kernel(const __half* __restrict__ Ab, int lda,
                      const __half* __restrict__ Bt,
                      const float* __restrict__ bias,
                      void* __restrict__ Cv, int ldc, int mode)
{
    extern __shared__ char smem[];
    const uint32_t s0 = smem_u32(smem);

    const int tid  = threadIdx.x;
    const int wid  = tid >> 5;
    const int lane = tid & 31;
    const int wm   = wid >> 1;
    const int wn   = wid & 1;
    const int bn   = blockIdx.x * GBN;
    const int bm0  = blockIdx.y * (MT_PER * GBM);

    const int lrow = tid >> 3;
    const int seg  = tid & 7;

    const int a_r  = (lane & 7) + ((lane >> 3) & 1) * 8;
    const int a_cb = (lane >> 4) * 16;
    const int b_r  = (lane & 7) + ((lane >> 4) & 1) * 8;
    const int b_cb = ((lane >> 3) & 1) * 16;

    auto issue = [&](int t) {
        const int mt = t / NCH, kc = t - mt * NCH;
        const int kp = kc * GKC;
        const uint32_t sa  = s0 + (t % NSTG) * STG_B;
        const uint32_t sbb = sa + A_ST;
        const size_t base = (size_t)(bm0 + mt * GBM);
#pragma unroll
        for (int i = 0; i < 4; ++i) {
            int r = lrow + i * 32;
            cp16(sa + r * ROWB + seg * 16,
                 Ab + (base + r) * lda + kp + seg * 8);
        }
#pragma unroll
        for (int i = 0; i < 4; ++i) {
            int r = lrow + i * 32;
            cp16(sbb + r * ROWB + seg * 16,
                 Bt + (size_t)(bn + r) * KDIM + kp + seg * 8);
        }
        cp_commit();
    };

    issue(0);
    issue(1);

    const int total = MT_PER * NCH;          // 12

    for (int mt = 0; mt < MT_PER; ++mt) {
        float acc[2][8][4];
#pragma unroll
        for (int i = 0; i < 2; ++i)
#pragma unroll
            for (int j = 0; j < 8; ++j)
#pragma unroll
                for (int q = 0; q < 4; ++q) acc[i][j][q] = 0.f;

        for (int kc = 0; kc < NCH; ++kc) {
            const int t = mt * NCH + kc;
            if (t < total - 1)
                asm volatile("cp.async.wait_group 1;" ::: "memory");
            else
                asm volatile("cp.async.wait_group 0;" ::: "memory");
            __syncthreads();

            if (t + 2 < total) issue(t + 2);

            const uint32_t sa = s0 + (t % NSTG) * STG_B;
            const uint32_t abase = sa + (wm * 32 + a_r) * ROWB + a_cb;
            const uint32_t bbase = sa + A_ST + (wn * 64 + b_r) * ROWB + b_cb;

#pragma unroll
            for (int ks = 0; ks < 4; ++ks) {
                const int kb = ks * 32;
                uint32_t af[2][4];
#pragma unroll
                for (int fm = 0; fm < 2; ++fm)
                    ldsm4(af[fm], abase + fm * 16 * ROWB + kb);
                uint32_t bfr[8][2];
#pragma unroll
                for (int j = 0; j < 4; ++j) {
                    uint32_t r[4];
                    ldsm4(r, bbase + j * 16 * ROWB + kb);
                    bfr[2 * j][0] = r[0]; bfr[2 * j][1] = r[1];
                    bfr[2 * j + 1][0] = r[2]; bfr[2 * j + 1][1] = r[3];
                }
#pragma unroll
                for (int fm = 0; fm < 2; ++fm)
#pragma unroll
                    for (int fn = 0; fn < 8; ++fn)
                        mma16816(acc[fm][fn], af[fm], bfr[fn]);
            }
        }

        const int bm = bm0 + mt * GBM;
#pragma unroll
        for (int fm = 0; fm < 2; ++fm) {
            const int row0 = bm + wm * 32 + fm * 16 + (lane >> 2);
            const int b0 = row0 / NTOK,        n0 = row0 - b0 * NTOK;
            const int b1 = (row0 + 8) / NTOK,  n1 = (row0 + 8) - b1 * NTOK;
#pragma unroll
            for (int fn = 0; fn < 8; ++fn) {
                const int col = bn + wn * 64 + fn * 8 + (lane & 3) * 2;
                const float b0f = __ldg(&bias[col]);
                const float b1f = __ldg(&bias[col + 1]);
                float o0 = acc[fm][fn][0] + b0f, o1 = acc[fm][fn][1] + b1f;
                float o2 = acc[fm][fn][2] + b0f, o3 = acc[fm][fn][3] + b1f;
                if (mode == 0) {
                    float* C = (float*)Cv;
                    *reinterpret_cast<float2*>(&C[(size_t)row0 * ldc + col]) =
                        make_float2(o0, o1);
                    *reinterpret_cast<float2*>(&C[(size_t)(row0 + 8) * ldc + col]) =
                        make_float2(o2, o3);
                } else if (col < 768) {
                    if (col < 384) {        // q: fold softmax scale here
                        o0 *= SCALE; o1 *= SCALE; o2 *= SCALE; o3 *= SCALE;
                    }
                    *reinterpret_cast<uint32_t*>(&g_qkh[(size_t)row0 * 768 + col]) =
                        pack2(__float2half_rn(o0), __float2half_rn(o1));
                    *reinterpret_cast<uint32_t*>(&g_qkh[(size_t)(row0 + 8) * 768 + col]) =
                        pack2(__float2half_rn(o2), __float2half_rn(o3));
                } else {
                    const int cv = col - 768;
                    const size_t i0 = ((size_t)b0 * CDIM + cv) * 64 + n0;
                    const size_t i1 = ((size_t)b1 * CDIM + cv) * 64 + n1;
                    g_vt[i0]      = __float2half_rn(o0);
                    g_vt[i0 + 64] = __float2half_rn(o1);
                    g_vt[i1]      = __float2half_rn(o2);
                    g_vt[i1 + 64] = __float2half_rn(o3);
                }
            }
        }
    }
}

// -------------------- MMA attention (scale pre-folded into q) ---------------
__global__ __launch_bounds__(128)
void attn_mma_kernel(const float* __restrict__ relb,
                     const float* __restrict__ mask)
{
    __shared__ float bias_s[NTOK * BSTR];

    const int w = blockIdx.x, h = blockIdx.y, zh = blockIdx.z;
    const int tid = threadIdx.x, warp = tid >> 5, lane = tid & 31;
    const int kq = lane >> 2;
    const int kc = (lane & 3) * 2;

    {
        const float* rb = relb + (size_t)h * NTOK * NTOK;
        const float* mk = mask + (size_t)w * NTOK * NTOK;
        for (int i = tid; i < NTOK * NTOK; i += 128)
            bias_s[(i / NTOK) * BSTR + (i % NTOK)] = rb[i] + mk[i];
    }
    __syncthreads();

    for (int win = 0; win < 4; ++win) {
        const int j = zh * 16 + warp * 4 + win;
        const int b = j * 64 + w;
        const __half* qk  = g_qkh + (size_t)b * NTOK * 768 + h * DHEAD;
        const __half* vth = g_vt + ((size_t)b * CDIM + h * DHEAD) * 64;

        uint32_t kf[7][2][2];
#pragma unroll
        for (int nt = 0; nt < 7; ++nt) {
            const int key = nt * 8 + kq;
            const bool ok = (key < NTOK);
            const __half* p = qk + (size_t)(ok ? key : 0) * 768 + 384;
#pragma unroll
            for (int ks = 0; ks < 2; ++ks) {
                const int d = ks * 16 + kc;
                kf[nt][ks][0] = ok ? *reinterpret_cast<const uint32_t*>(p + d)     : 0u;
                kf[nt][ks][1] = ok ? *reinterpret_cast<const uint32_t*>(p + d + 8) : 0u;
            }
        }
        uint32_t vhf[4][4][2];
#pragma unroll
        for (int nt = 0; nt < 4; ++nt) {
            const size_t drow = (size_t)(nt * 8 + kq) * 64;
#pragma unroll
            for (int kt = 0; kt < 4; ++kt) {
#pragma unroll
                for (int r2 = 0; r2 < 2; ++r2) {
                    const int k0 = kt * 16 + kc + r2 * 8;
                    vhf[nt][kt][r2] = *reinterpret_cast<const uint32_t*>(vth + drow + k0);
                }
            }
        }

        for (int mt = 0; mt < 4; ++mt) {
            const int row = mt * 16 + kq;
            const bool r0ok = (row < NTOK), r1ok = (row + 8 < NTOK);
            const __half* q0 = qk + (size_t)(r0ok ? row : 0) * 768;
            const __half* q1 = qk + (size_t)(r1ok ? row + 8 : 0) * 768;

            uint32_t qf[2][4];
#pragma unroll
            for (int ks = 0; ks < 2; ++ks) {
                const int d = ks * 16 + kc;
                qf[ks][0] = r0ok ? *reinterpret_cast<const uint32_t*>(q0 + d)     : 0u;
                qf[ks][1] = r1ok ? *reinterpret_cast<const uint32_t*>(q1 + d)     : 0u;
                qf[ks][2] = r0ok ? *reinterpret_cast<const uint32_t*>(q0 + d + 8) : 0u;
                qf[ks][3] = r1ok ? *reinterpret_cast<const uint32_t*>(q1 + d + 8) : 0u;
            }

            float sf[7][4];
#pragma unroll
            for (int nt = 0; nt < 7; ++nt) {
                sf[nt][0] = sf[nt][1] = sf[nt][2] = sf[nt][3] = 0.f;
                mma16816(sf[nt], qf[0], kf[nt][0]);
                mma16816(sf[nt], qf[1], kf[nt][1]);
            }

            const int n0 = (row < 48) ? row : 48;
            const int n1 = (row + 8 < 48) ? (row + 8) : 48;
            float sum0 = 0.f, sum1 = 0.f;
#pragma unroll
            for (int nt = 0; nt < 7; ++nt) {
                const int key = nt * 8 + kc;
                const float2 bq0 = *reinterpret_cast<const float2*>(&bias_s[n0 * BSTR + key]);
                const float2 bq1 = *reinterpret_cast<const float2*>(&bias_s[n1 * BSTR + key]);
                float e0 = __expf(sf[nt][0] + bq0.x);
                float e1 = __expf(sf[nt][1] + bq0.y);
                float e2 = __expf(sf[nt][2] + bq1.x);
                float e3 = __expf(sf[nt][3] + bq1.y);
                if (nt == 6) {
                    if (kc != 0) { e0 = 0.f; e2 = 0.f; }
                    e1 = 0.f; e3 = 0.f;
                }
                sf[nt][0] = e0; sf[nt][1] = e1; sf[nt][2] = e2; sf[nt][3] = e3;
                sum0 += e0 + e1; sum1 += e2 + e3;
            }
            sum0 += __shfl_xor_sync(0xffffffffu, sum0, 1);
            sum0 += __shfl_xor_sync(0xffffffffu, sum0, 2);
            sum1 += __shfl_xor_sync(0xffffffffu, sum1, 1);
            sum1 += __shfl_xor_sync(0xffffffffu, sum1, 2);
            const float inv0 = 1.f / sum0, inv1 = 1.f / sum1;

            float of[4][4];
#pragma unroll
            for (int nt = 0; nt < 4; ++nt)
                of[nt][0] = of[nt][1] = of[nt][2] = of[nt][3] = 0.f;

#pragma unroll
            for (int kt = 0; kt < 4; ++kt) {
                float e[8];
                e[0] = sf[2 * kt][0]; e[1] = sf[2 * kt][1];
                e[2] = sf[2 * kt][2]; e[3] = sf[2 * kt][3];
                if (2 * kt + 1 < 7) {
                    e[4] = sf[2 * kt + 1][0]; e[5] = sf[2 * kt + 1][1];
                    e[6] = sf[2 * kt + 1][2]; e[7] = sf[2 * kt + 1][3];
                } else {
                    e[4] = e[5] = e[6] = e[7] = 0.f;
                }
                __half hb[8], lb[8];
#pragma unroll
                for (int i = 0; i < 8; ++i) {
                    hb[i] = __float2half_rn(e[i]);
                    lb[i] = __float2half_rn(e[i] - __half2float(hb[i]));
                }
                uint32_t ph[4], pl[4];
                ph[0] = pack2(hb[0], hb[1]); ph[1] = pack2(hb[2], hb[3]);
                ph[2] = pack2(hb[4], hb[5]); ph[3] = pack2(hb[6], hb[7]);
                pl[0] = pack2(lb[0], lb[1]); pl[1] = pack2(lb[2], lb[3]);
                pl[2] = pack2(lb[4], lb[5]); pl[3] = pack2(lb[6], lb[7]);
#pragma unroll
                for (int nt = 0; nt < 4; ++nt) {
                    mma16816(of[nt], ph, vhf[nt][kt]);
                    mma16816(of[nt], pl, vhf[nt][kt]);
                }
            }

            const size_t r0 = ((size_t)b * NTOK + row) * CDIM + h * DHEAD;
            const size_t r1 = ((size_t)b * NTOK + row + 8) * CDIM + h * DHEAD;
#pragma unroll
            for (int nt = 0; nt < 4; ++nt) {
                const int d = nt * 8 + kc;
                if (r0ok) {
                    *reinterpret_cast<uint32_t*>(&g_attf[r0 + d]) =
                        pack2(__float2half_rn(of[nt][0] * inv0),
                              __float2half_rn(of[nt][1] * inv0));
                }
                if (r1ok) {
                    *reinterpret_cast<uint32_t*>(&g_attf[r1 + d]) =
                        pack2(__float2half_rn(of[nt][2] * inv1),
                              __float2half_rn(of[nt][3] * inv1));
                }
            }
        }
    }
}

// ---------------------------------------------------------------------------
extern "C" void kernel_launch(void* const* d_in, const int* in_sizes, int n_in,
                              void* d_out, int out_size)
{
    const float* x      = (const float*)d_in[0];
    const float* mask   = (const float*)d_in[1];
    const float* qkv_w  = (const float*)d_in[2];
    const float* qkv_b  = (const float*)d_in[3];
    const float* proj_w = (const float*)d_in[4];
    const float* proj_b = (const float*)d_in[5];
    const float* relb   = (const float*)d_in[6];
    float* out = (float*)d_out;

    void *p_xh, *p_attf, *p_wq, *p_wp;
    cudaGetSymbolAddress(&p_xh,   g_xh);
    cudaGetSymbolAddress(&p_attf, g_attf);
    cudaGetSymbolAddress(&p_wq,   g_wq);
    cudaGetSymbolAddress(&p_wp,   g_wp);

    cudaFuncSetAttribute(gemm_fp16_kernel,
                         cudaFuncAttributeMaxDynamicSharedMemorySize, SMEM_GEMM);

    // 0) fused preps
    prep_all_kernel<<<PX_BLKS + WQ_BLKS + WP_BLKS + PAD_BLKS, 256>>>(x, qkv_w, proj_w);

    // 1) fused QKV GEMM (2 chained M-tiles per CTA)
    {
        dim3 grid(QKVC / GBN, MTILES / MT_PER);   // 9 x 392
        gemm_fp16_kernel<<<grid, 256, SMEM_GEMM>>>(
            (const __half*)p_xh, KDIM, (const __half*)p_wq,
            qkv_b, nullptr, 0, 3);
    }
    // 2) MMA attention
    {
        dim3 grid(NWIN, HNUM, 2);
        attn_mma_kernel<<<grid, 128>>>(relb, mask);
    }
    // 3) projection GEMM (2 chained M-tiles per CTA)
    {
        dim3 grid(CDIM / GBN, MTILES / MT_PER);   // 3 x 392
        gemm_fp16_kernel<<<grid, 256, SMEM_GEMM>>>(
            (const __half*)p_attf, CDIM, (const __half*)p_wp,
            proj_b, out, CDIM, 0);
    }
}

// round 15
// speedup vs baseline: 1.1528x; 1.0498x over previous
#include <cuda_runtime.h>
#include <cuda_fp16.h>
#include <cstdint>

// Problem constants: B_=2048, N=49, C=384, H=12, d=32, nW=64
#define BWIN   2048
#define NTOK   49
#define CDIM   384
#define HNUM   12
#define DHEAD  32
#define NWIN   64
#define MROWS  (BWIN * NTOK)     // 100352
#define QKVC   (3 * CDIM)        // 1152
#define KDIM   384

// GEMM tiling (R12 shape: 128x128 tile, 1 M-tile/CTA, 2 CTAs/SM)
#define GBM   128
#define GBN   128
#define GKC   64
#define NCH   6                  // 384 / 64
#define NSTG  3
#define ROWB  144
#define A_ST  (GBM * ROWB)
#define B_ST  (GBN * ROWB)
#define STG_B (A_ST + B_ST)
#define SMEM_GEMM (NSTG * STG_B) // 110592 -> 2 CTAs/SM
#define MTILES (MROWS / GBM)     // 784

#define PX_BLKS  37632
#define WQ_BLKS  1728
#define WP_BLKS  576
#define PAD_BLKS 6144

#define BSTR 50
#define SCALE 0.17677669529663687f

// -------------------- device scratch --------------------------------------
__device__ __align__(16) __half g_xh  [(size_t)MROWS * KDIM];
__device__ __align__(16) __half g_attf[(size_t)MROWS * CDIM];
__device__ __align__(16) __half g_qkh [(size_t)MROWS * 768];
__device__ __align__(16) __half g_vt  [(size_t)BWIN * CDIM * 64];
__device__ __align__(16) __half g_wq  [(size_t)QKVC * KDIM];
__device__ __align__(16) __half g_wp  [(size_t)CDIM * KDIM];

// -------------------- PTX helpers -----------------------------------------
__device__ __forceinline__ uint32_t smem_u32(const void* p) {
    uint32_t a;
    asm("{ .reg .u64 t; cvta.to.shared.u64 t, %1; cvt.u32.u64 %0, t; }"
        : "=r"(a) : "l"(p));
    return a;
}
__device__ __forceinline__ void cp16(uint32_t s, const void* g) {
    asm volatile("cp.async.cg.shared.global [%0], [%1], 16;" :: "r"(s), "l"(g));
}
__device__ __forceinline__ void cp_commit() {
    asm volatile("cp.async.commit_group;" ::: "memory");
}
__device__ __forceinline__ void ldsm4(uint32_t* r, uint32_t addr) {
    asm volatile("ldmatrix.sync.aligned.m8n8.x4.shared.b16 {%0,%1,%2,%3}, [%4];"
        : "=r"(r[0]), "=r"(r[1]), "=r"(r[2]), "=r"(r[3]) : "r"(addr));
}
__device__ __forceinline__ void mma16816(float* d, const uint32_t* a, const uint32_t* b) {
    asm volatile(
        "mma.sync.aligned.m16n8k16.row.col.f32.f16.f16.f32 "
        "{%0,%1,%2,%3}, {%4,%5,%6,%7}, {%8,%9}, {%0,%1,%2,%3};"
        : "+f"(d[0]), "+f"(d[1]), "+f"(d[2]), "+f"(d[3])
        : "r"(a[0]), "r"(a[1]), "r"(a[2]), "r"(a[3]), "r"(b[0]), "r"(b[1]));
}
__device__ __forceinline__ uint32_t pack2(__half lo, __half hi) {
    return (uint32_t)__half_as_ushort(lo) | ((uint32_t)__half_as_ushort(hi) << 16);
}

// -------------------- fused prep -------------------------------------------
__global__ __launch_bounds__(256)
void prep_all_kernel(const float* __restrict__ x,
                     const float* __restrict__ qkv_w,
                     const float* __restrict__ proj_w)
{
    const int bid = blockIdx.x;
    const int tid = threadIdx.x;

    if (bid < PX_BLKS) {
        size_t id = (size_t)bid * 256 + tid;
        size_t row = id / 96;
        int c4 = (int)(id % 96) * 4;
        float4 v = *reinterpret_cast<const float4*>(&x[row * KDIM + c4]);
        __half h[4];
        h[0] = __float2half_rn(v.x); h[1] = __float2half_rn(v.y);
        h[2] = __float2half_rn(v.z); h[3] = __float2half_rn(v.w);
        *reinterpret_cast<uint2*>(&g_xh[row * KDIM + c4]) = *reinterpret_cast<uint2*>(h);
    } else if (bid < PX_BLKS + WQ_BLKS) {
        int id = (bid - PX_BLKS) * 256 + tid;
        if (id < KDIM * QKVC) {
            int k = id / QKVC, n = id % QKVC;
            g_wq[(size_t)n * KDIM + k] = __float2half_rn(qkv_w[(size_t)k * QKVC + n]);
        }
    } else if (bid < PX_BLKS + WQ_BLKS + WP_BLKS) {
        int id = (bid - PX_BLKS - WQ_BLKS) * 256 + tid;
        if (id < KDIM * CDIM) {
            int k = id / CDIM, n = id % CDIM;
            g_wp[(size_t)n * KDIM + k] = __float2half_rn(proj_w[(size_t)k * CDIM + n]);
        }
    } else {
        size_t s = (size_t)(bid - PX_BLKS - WQ_BLKS - WP_BLKS) * 256 + tid;
        size_t row = s >> 1;
        if (row < (size_t)BWIN * CDIM) {
            uint4* p = reinterpret_cast<uint4*>(
                reinterpret_cast<char*>(g_vt) + row * 128 + 96 + (s & 1) * 16);
            *p = make_uint4(0, 0, 0, 0);
        }
    }
}

// -------------------- GEMM (exact R12 shape; q-scale folded) ----------------
// mode 0: fp32 out to Cv (ldc stride)                         (proj)
// mode 3: qkv fused — col<384: q*SCALE fp16 -> g_qkh;
//                     384<=col<768: k fp16 -> g_qkh;
//                     col>=768: v fp16 scatter -> g_vt
__global__ __launch_bounds__(256, 2)
void gemm_fp16_kernel(const __half* __restrict__ Ab, int lda,
                      const __half* __restrict__ Bt,
                      const float* __restrict__ bias,
                      void* __restrict__ Cv, int ldc, int mode)
{
    extern __shared__ char smem[];
    const uint32_t s0 = smem_u32(smem);

    const int tid  = threadIdx.x;
    const int wid  = tid >> 5;
    const int lane = tid & 31;
    const int wm   = wid >> 1;
    const int wn   = wid & 1;
    const int bn   = blockIdx.x * GBN;
    const int bm   = blockIdx.y * GBM;

    const int lrow = tid >> 3;
    const int seg  = tid & 7;

    float acc[2][8][4];
#pragma unroll
    for (int i = 0; i < 2; ++i)
#pragma unroll
        for (int j = 0; j < 8; ++j)
#pragma unroll
            for (int q = 0; q < 4; ++q) acc[i][j][q] = 0.f;

    const int a_r  = (lane & 7) + ((lane >> 3) & 1) * 8;
    const int a_cb = (lane >> 4) * 16;
    const int b_r  = (lane & 7) + ((lane >> 4) & 1) * 8;
    const int b_cb = ((lane >> 3) & 1) * 16;

    auto issue = [&](int kc, int stg) {
        const int kp = kc * GKC;
        const uint32_t sa  = s0 + stg * STG_B;
        const uint32_t sbb = sa + A_ST;
#pragma unroll
        for (int i = 0; i < 4; ++i) {
            int r = lrow + i * 32;
            cp16(sa + r * ROWB + seg * 16,
                 Ab + (size_t)(bm + r) * lda + kp + seg * 8);
        }
#pragma unroll
        for (int i = 0; i < 4; ++i) {
            int r = lrow + i * 32;
            cp16(sbb + r * ROWB + seg * 16,
                 Bt + (size_t)(bn + r) * KDIM + kp + seg * 8);
        }
        cp_commit();
    };

    issue(0, 0);
    issue(1, 1);

    for (int kc = 0; kc < NCH; ++kc) {
        if (kc < NCH - 1)
            asm volatile("cp.async.wait_group 1;" ::: "memory");
        else
            asm volatile("cp.async.wait_group 0;" ::: "memory");
        __syncthreads();

        if (kc + 2 < NCH) issue(kc + 2, (kc + 2) % NSTG);

        const uint32_t sa = s0 + (kc % NSTG) * STG_B;
        const uint32_t abase = sa + (wm * 32 + a_r) * ROWB + a_cb;
        const uint32_t bbase = sa + A_ST + (wn * 64 + b_r) * ROWB + b_cb;

#pragma unroll
        for (int ks = 0; ks < 4; ++ks) {
            const int kb = ks * 32;
            uint32_t af[2][4];
#pragma unroll
            for (int fm = 0; fm < 2; ++fm)
                ldsm4(af[fm], abase + fm * 16 * ROWB + kb);
            uint32_t bfr[8][2];
#pragma unroll
            for (int j = 0; j < 4; ++j) {
                uint32_t r[4];
                ldsm4(r, bbase + j * 16 * ROWB + kb);
                bfr[2 * j][0] = r[0]; bfr[2 * j][1] = r[1];
                bfr[2 * j + 1][0] = r[2]; bfr[2 * j + 1][1] = r[3];
            }
#pragma unroll
            for (int fm = 0; fm < 2; ++fm)
#pragma unroll
                for (int fn = 0; fn < 8; ++fn)
                    mma16816(acc[fm][fn], af[fm], bfr[fn]);
        }
    }

#pragma unroll
    for (int fm = 0; fm < 2; ++fm) {
        const int row0 = bm + wm * 32 + fm * 16 + (lane >> 2);
        const int b0 = row0 / NTOK,        n0 = row0 - b0 * NTOK;
        const int b1 = (row0 + 8) / NTOK,  n1 = (row0 + 8) - b1 * NTOK;
#pragma unroll
        for (int fn = 0; fn < 8; ++fn) {
            const int col = bn + wn * 64 + fn * 8 + (lane & 3) * 2;
            const float b0f = __ldg(&bias[col]);
            const float b1f = __ldg(&bias[col + 1]);
            float o0 = acc[fm][fn][0] + b0f, o1 = acc[fm][fn][1] + b1f;
            float o2 = acc[fm][fn][2] + b0f, o3 = acc[fm][fn][3] + b1f;
            if (mode == 0) {
                float* C = (float*)Cv;
                *reinterpret_cast<float2*>(&C[(size_t)row0 * ldc + col]) =
                    make_float2(o0, o1);
                *reinterpret_cast<float2*>(&C[(size_t)(row0 + 8) * ldc + col]) =
                    make_float2(o2, o3);
            } else if (col < 768) {
                if (col < 384) {        // q: fold softmax scale here
                    o0 *= SCALE; o1 *= SCALE; o2 *= SCALE; o3 *= SCALE;
                }
                *reinterpret_cast<uint32_t*>(&g_qkh[(size_t)row0 * 768 + col]) =
                    pack2(__float2half_rn(o0), __float2half_rn(o1));
                *reinterpret_cast<uint32_t*>(&g_qkh[(size_t)(row0 + 8) * 768 + col]) =
                    pack2(__float2half_rn(o2), __float2half_rn(o3));
            } else {
                const int cv = col - 768;
                const size_t i0 = ((size_t)b0 * CDIM + cv) * 64 + n0;
                const size_t i1 = ((size_t)b1 * CDIM + cv) * 64 + n1;
                g_vt[i0]      = __float2half_rn(o0);
                g_vt[i0 + 64] = __float2half_rn(o1);
                g_vt[i1]      = __float2half_rn(o2);
                g_vt[i1 + 64] = __float2half_rn(o3);
            }
        }
    }
}

// -------------------- MMA attention: 8 warps/block, bias staged once --------
__global__ __launch_bounds__(256)
void attn_mma_kernel(const float* __restrict__ relb,
                     const float* __restrict__ mask)
{
    __shared__ float bias_s[NTOK * BSTR];

    const int w = blockIdx.x, h = blockIdx.y;
    const int tid = threadIdx.x, warp = tid >> 5, lane = tid & 31;
    const int kq = lane >> 2;
    const int kc = (lane & 3) * 2;

    {
        const float* rb = relb + (size_t)h * NTOK * NTOK;
        const float* mk = mask + (size_t)w * NTOK * NTOK;
        for (int i = tid; i < NTOK * NTOK; i += 256)
            bias_s[(i / NTOK) * BSTR + (i % NTOK)] = rb[i] + mk[i];
    }
    __syncthreads();

    for (int win = 0; win < 4; ++win) {
        const int j = warp * 4 + win;            // 0..31
        const int b = j * 64 + w;
        const __half* qk  = g_qkh + (size_t)b * NTOK * 768 + h * DHEAD;
        const __half* vth = g_vt + ((size_t)b * CDIM + h * DHEAD) * 64;

        uint32_t kf[7][2][2];
#pragma unroll
        for (int nt = 0; nt < 7; ++nt) {
            const int key = nt * 8 + kq;
            const bool ok = (key < NTOK);
            const __half* p = qk + (size_t)(ok ? key : 0) * 768 + 384;
#pragma unroll
            for (int ks = 0; ks < 2; ++ks) {
                const int d = ks * 16 + kc;
                kf[nt][ks][0] = ok ? *reinterpret_cast<const uint32_t*>(p + d)     : 0u;
                kf[nt][ks][1] = ok ? *reinterpret_cast<const uint32_t*>(p + d + 8) : 0u;
            }
        }
        uint32_t vhf[4][4][2];
#pragma unroll
        for (int nt = 0; nt < 4; ++nt) {
            const size_t drow = (size_t)(nt * 8 + kq) * 64;
#pragma unroll
            for (int kt = 0; kt < 4; ++kt) {
#pragma unroll
                for (int r2 = 0; r2 < 2; ++r2) {
                    const int k0 = kt * 16 + kc + r2 * 8;
                    vhf[nt][kt][r2] = *reinterpret_cast<const uint32_t*>(vth + drow + k0);
                }
            }
        }

        for (int mt = 0; mt < 4; ++mt) {
            const int row = mt * 16 + kq;
            const bool r0ok = (row < NTOK), r1ok = (row + 8 < NTOK);
            const __half* q0 = qk + (size_t)(r0ok ? row : 0) * 768;
            const __half* q1 = qk + (size_t)(r1ok ? row + 8 : 0) * 768;

            uint32_t qf[2][4];
#pragma unroll
            for (int ks = 0; ks < 2; ++ks) {
                const int d = ks * 16 + kc;
                qf[ks][0] = r0ok ? *reinterpret_cast<const uint32_t*>(q0 + d)     : 0u;
                qf[ks][1] = r1ok ? *reinterpret_cast<const uint32_t*>(q1 + d)     : 0u;
                qf[ks][2] = r0ok ? *reinterpret_cast<const uint32_t*>(q0 + d + 8) : 0u;
                qf[ks][3] = r1ok ? *reinterpret_cast<const uint32_t*>(q1 + d + 8) : 0u;
            }

            float sf[7][4];
#pragma unroll
            for (int nt = 0; nt < 7; ++nt) {
                sf[nt][0] = sf[nt][1] = sf[nt][2] = sf[nt][3] = 0.f;
                mma16816(sf[nt], qf[0], kf[nt][0]);
                mma16816(sf[nt], qf[1], kf[nt][1]);
            }

            const int n0 = (row < 48) ? row : 48;
            const int n1 = (row + 8 < 48) ? (row + 8) : 48;
            float sum0 = 0.f, sum1 = 0.f;
#pragma unroll
            for (int nt = 0; nt < 7; ++nt) {
                const int key = nt * 8 + kc;
                const float2 bq0 = *reinterpret_cast<const float2*>(&bias_s[n0 * BSTR + key]);
                const float2 bq1 = *reinterpret_cast<const float2*>(&bias_s[n1 * BSTR + key]);
                float e0 = __expf(sf[nt][0] + bq0.x);
                float e1 = __expf(sf[nt][1] + bq0.y);
                float e2 = __expf(sf[nt][2] + bq1.x);
                float e3 = __expf(sf[nt][3] + bq1.y);
                if (nt == 6) {
                    if (kc != 0) { e0 = 0.f; e2 = 0.f; }
                    e1 = 0.f; e3 = 0.f;
                }
                sf[nt][0] = e0; sf[nt][1] = e1; sf[nt][2] = e2; sf[nt][3] = e3;
                sum0 += e0 + e1; sum1 += e2 + e3;
            }
            sum0 += __shfl_xor_sync(0xffffffffu, sum0, 1);
            sum0 += __shfl_xor_sync(0xffffffffu, sum0, 2);
            sum1 += __shfl_xor_sync(0xffffffffu, sum1, 1);
            sum1 += __shfl_xor_sync(0xffffffffu, sum1, 2);
            const float inv0 = 1.f / sum0, inv1 = 1.f / sum1;

            float of[4][4];
#pragma unroll
            for (int nt = 0; nt < 4; ++nt)
                of[nt][0] = of[nt][1] = of[nt][2] = of[nt][3] = 0.f;

#pragma unroll
            for (int kt = 0; kt < 4; ++kt) {
                float e[8];
                e[0] = sf[2 * kt][0]; e[1] = sf[2 * kt][1];
                e[2] = sf[2 * kt][2]; e[3] = sf[2 * kt][3];
                if (2 * kt + 1 < 7) {
                    e[4] = sf[2 * kt + 1][0]; e[5] = sf[2 * kt + 1][1];
                    e[6] = sf[2 * kt + 1][2]; e[7] = sf[2 * kt + 1][3];
                } else {
                    e[4] = e[5] = e[6] = e[7] = 0.f;
                }
                __half hb[8], lb[8];
#pragma unroll
                for (int i = 0; i < 8; ++i) {
                    hb[i] = __float2half_rn(e[i]);
                    lb[i] = __float2half_rn(e[i] - __half2float(hb[i]));
                }
                uint32_t ph[4], pl[4];
                ph[0] = pack2(hb[0], hb[1]); ph[1] = pack2(hb[2], hb[3]);
                ph[2] = pack2(hb[4], hb[5]); ph[3] = pack2(hb[6], hb[7]);
                pl[0] = pack2(lb[0], lb[1]); pl[1] = pack2(lb[2], lb[3]);
                pl[2] = pack2(lb[4], lb[5]); pl[3] = pack2(lb[6], lb[7]);
#pragma unroll
                for (int nt = 0; nt < 4; ++nt) {
                    mma16816(of[nt], ph, vhf[nt][kt]);
                    mma16816(of[nt], pl, vhf[nt][kt]);
                }
            }

            const size_t r0 = ((size_t)b * NTOK + row) * CDIM + h * DHEAD;
            const size_t r1 = ((size_t)b * NTOK + row + 8) * CDIM + h * DHEAD;
#pragma unroll
            for (int nt = 0; nt < 4; ++nt) {
                const int d = nt * 8 + kc;
                if (r0ok) {
                    *reinterpret_cast<uint32_t*>(&g_attf[r0 + d]) =
                        pack2(__float2half_rn(of[nt][0] * inv0),
                              __float2half_rn(of[nt][1] * inv0));
                }
                if (r1ok) {
                    *reinterpret_cast<uint32_t*>(&g_attf[r1 + d]) =
                        pack2(__float2half_rn(of[nt][2] * inv1),
                              __float2half_rn(of[nt][3] * inv1));
                }
            }
        }
    }
}

// ---------------------------------------------------------------------------
extern "C" void kernel_launch(void* const* d_in, const int* in_sizes, int n_in,
                              void* d_out, int out_size)
{
    const float* x      = (const float*)d_in[0];
    const float* mask   = (const float*)d_in[1];
    const float* qkv_w  = (const float*)d_in[2];
    const float* qkv_b  = (const float*)d_in[3];
    const float* proj_w = (const float*)d_in[4];
    const float* proj_b = (const float*)d_in[5];
    const float* relb   = (const float*)d_in[6];
    float* out = (float*)d_out;

    void *p_xh, *p_attf, *p_wq, *p_wp;
    cudaGetSymbolAddress(&p_xh,   g_xh);
    cudaGetSymbolAddress(&p_attf, g_attf);
    cudaGetSymbolAddress(&p_wq,   g_wq);
    cudaGetSymbolAddress(&p_wp,   g_wp);

    cudaFuncSetAttribute(gemm_fp16_kernel,
                         cudaFuncAttributeMaxDynamicSharedMemorySize, SMEM_GEMM);

    // 0) fused preps
    prep_all_kernel<<<PX_BLKS + WQ_BLKS + WP_BLKS + PAD_BLKS, 256>>>(x, qkv_w, proj_w);

    // 1) fused QKV GEMM (R12 shape)
    {
        dim3 grid(QKVC / GBN, MTILES);    // 9 x 784
        gemm_fp16_kernel<<<grid, 256, SMEM_GEMM>>>(
            (const __half*)p_xh, KDIM, (const __half*)p_wq,
            qkv_b, nullptr, 0, 3);
    }
    // 2) MMA attention (8 warps/block, bias staged once per (w,h))
    {
        dim3 grid(NWIN, HNUM);
        attn_mma_kernel<<<grid, 256>>>(relb, mask);
    }
    // 3) projection GEMM (R12 shape)
    {
        dim3 grid(CDIM / GBN, MTILES);    // 3 x 784
        gemm_fp16_kernel<<<grid, 256, SMEM_GEMM>>>(
            (const __half*)p_attf, CDIM, (const __half*)p_wp,
            proj_b, out, CDIM, 0);
    }
}